// round 1
// baseline (speedup 1.0000x reference)
#include <cuda_runtime.h>
#include <cstdint>

#define QBF   127.0f
#define EPSA  1e-5f

// ---------------- device scratch (no allocations allowed) ----------------
__device__ __align__(16) signed char g_W1q[128 * 256];
__device__ __align__(16) signed char g_W2q[128 * 128];
__device__ float g_wscale1;
__device__ float g_wscale2;
__device__ float g_norm[8 * 128];

// ---------------- smem layout for the main kernel ----------------
#define XS 272      // byte stride for 256-byte int8 rows (+16B pad, conflict-free ldmatrix)
#define HS 144      // byte stride for 128-byte int8 rows (+16B pad)
#define OFF_X   0
#define OFF_W1  34816
#define OFF_W2  69632
#define OFF_H   88064
#define OFF_S1  106496
#define OFF_B1  107008
#define OFF_B2  107520
#define OFF_CS  108032
#define SMEM_BYTES 108544

// ---------------- PTX helpers ----------------
__device__ __forceinline__ void ldsm4(uint32_t &r0, uint32_t &r1, uint32_t &r2, uint32_t &r3,
                                      uint32_t addr) {
    asm volatile("ldmatrix.sync.aligned.m8n8.x4.shared.b16 {%0,%1,%2,%3}, [%4];"
                 : "=r"(r0), "=r"(r1), "=r"(r2), "=r"(r3) : "r"(addr));
}
__device__ __forceinline__ void ldsm2(uint32_t &r0, uint32_t &r1, uint32_t addr) {
    asm volatile("ldmatrix.sync.aligned.m8n8.x2.shared.b16 {%0,%1}, [%2];"
                 : "=r"(r0), "=r"(r1) : "r"(addr));
}
__device__ __forceinline__ void imma(int *c, uint32_t a0, uint32_t a1, uint32_t a2, uint32_t a3,
                                     uint32_t b0, uint32_t b1) {
    asm volatile("mma.sync.aligned.m16n8k32.row.col.s32.s8.s8.s32 "
                 "{%0,%1,%2,%3},{%4,%5,%6,%7},{%8,%9},{%0,%1,%2,%3};"
                 : "+r"(c[0]), "+r"(c[1]), "+r"(c[2]), "+r"(c[3])
                 : "r"(a0), "r"(a1), "r"(a2), "r"(a3), "r"(b0), "r"(b1));
}

__device__ __forceinline__ unsigned q4(float4 v, float s) {
    int a = (int)fminf(fmaxf(rintf(v.x * s), -128.f), 127.f);
    int b = (int)fminf(fmaxf(rintf(v.y * s), -128.f), 127.f);
    int c = (int)fminf(fmaxf(rintf(v.z * s), -128.f), 127.f);
    int d = (int)fminf(fmaxf(rintf(v.w * s), -128.f), 127.f);
    return (unsigned)(a & 255) | ((unsigned)(b & 255) << 8) |
           ((unsigned)(c & 255) << 16) | ((unsigned)(d & 255) << 24);
}

// ---------------- prep: ternary weight quant + zero normalizer ----------------
__global__ void prep_kernel(const float* __restrict__ W1, const float* __restrict__ W2) {
    __shared__ double red[256];
    int tid = threadIdx.x;
    const float* W = (blockIdx.x == 0) ? W1 : W2;
    int n = (blockIdx.x == 0) ? 128 * 256 : 128 * 128;
    signed char* dst = (blockIdx.x == 0) ? g_W1q : g_W2q;

    double s = 0.0;
    for (int i = tid; i < n; i += 256) s += (double)fabsf(W[i]);
    red[tid] = s;
    __syncthreads();
    for (int st = 128; st > 0; st >>= 1) {
        if (tid < st) red[tid] += red[tid + st];
        __syncthreads();
    }
    float wsc = fmaxf((float)(red[0] / (double)n), EPSA);  // = 1/ws = clip(mean|W|, eps)
    if (tid == 0) {
        if (blockIdx.x == 0) g_wscale1 = wsc; else g_wscale2 = wsc;
    }
    float ws = 1.0f / wsc;
    for (int i = tid; i < n; i += 256) {
        float q = fminf(fmaxf(rintf(W[i] * ws), -1.f), 1.f);
        dst[i] = (signed char)(int)q;
    }
    if (blockIdx.x == 1)
        for (int i = tid; i < 8 * 128; i += 256) g_norm[i] = 0.f;
}

// ---------------- fused main: quant -> IMMA GEMM1 -> relu/requant -> IMMA GEMM2
//                  -> sigmoid -> pu = prior * like -> colsum atomics ----------------
__global__ void __launch_bounds__(256, 2)
main_kernel(const float* __restrict__ evidence, const float* __restrict__ prior,
            const float* __restrict__ b1, const float* __restrict__ b2,
            float* __restrict__ out) {
    extern __shared__ char smem[];
    uint32_t sb = (uint32_t)__cvta_generic_to_shared(smem);
    float* sS  = (float*)(smem + OFF_S1);
    float* sB1 = (float*)(smem + OFF_B1);
    float* sB2 = (float*)(smem + OFF_B2);
    float* sCS = (float*)(smem + OFF_CS);

    int tid = threadIdx.x, lane = tid & 31, w = tid >> 5;
    int tok0 = blockIdx.x * 128;

    // ---- phase 0: stage quantized weights + biases into smem ----
    for (int i = tid; i < 128 * 16; i += 256) {
        int r = i >> 4, c = i & 15;
        *(int4*)(smem + OFF_W1 + r * XS + c * 16) = *(const int4*)(g_W1q + r * 256 + c * 16);
    }
    for (int i = tid; i < 128 * 8; i += 256) {
        int r = i >> 3, c = i & 7;
        *(int4*)(smem + OFF_W2 + r * HS + c * 16) = *(const int4*)(g_W2q + r * 128 + c * 16);
    }
    if (tid < 128) { sB1[tid] = b1[tid]; sB2[tid] = b2[tid]; sCS[tid] = 0.f; }

    // ---- phase 1: per-token absmax int8 quant of concat([prior, evidence]) ----
    // warp w owns rows [16w, 16w+16); one 256-float row per full-warp iteration.
    float wsc1 = g_wscale1;
    for (int rg = 0; rg < 4; rg++) {
        int rbase = 16 * w + rg * 4;
        float4 pv[4], ev[4];
#pragma unroll
        for (int j = 0; j < 4; j++) {
            long gr = (long)(tok0 + rbase + j) * 128;
            pv[j] = *(const float4*)(prior + gr + lane * 4);
            ev[j] = *(const float4*)(evidence + gr + lane * 4);
        }
#pragma unroll
        for (int j = 0; j < 4; j++) {
            float m = fmaxf(fmaxf(fmaxf(fabsf(pv[j].x), fabsf(pv[j].y)),
                                  fmaxf(fabsf(pv[j].z), fabsf(pv[j].w))),
                            fmaxf(fmaxf(fabsf(ev[j].x), fabsf(ev[j].y)),
                                  fmaxf(fabsf(ev[j].z), fabsf(ev[j].w))));
#pragma unroll
            for (int o = 16; o; o >>= 1) m = fmaxf(m, __shfl_xor_sync(0xffffffffu, m, o));
            float mc = fmaxf(m, EPSA);
            float s = QBF / mc;
            int r = rbase + j;
            if (lane == 0) sS[r] = mc * wsc1 * (1.0f / QBF);
            *(unsigned*)(smem + OFF_X + r * XS + lane * 4)       = q4(pv[j], s);
            *(unsigned*)(smem + OFF_X + r * XS + 128 + lane * 4) = q4(ev[j], s);
        }
    }
    __syncthreads();

    // ---- GEMM1: [16 x 256] x [256 x 128] per warp, exact int8 ----
    int acc[16][4];
#pragma unroll
    for (int nt = 0; nt < 16; nt++)
#pragma unroll
        for (int i = 0; i < 4; i++) acc[nt][i] = 0;

    int g = lane >> 2;      // 0..7 (row group)
    int t = lane & 3;       // 0..3 (col pair)
    {
        int arow = 16 * w + (lane & 7) + ((lane >> 3) & 1) * 8;
        uint32_t abase = sb + OFF_X + arow * XS + (lane >> 4) * 16;
        int brow = lane & 7;
        int bkoff = ((lane >> 3) & 1) * 16;
#pragma unroll
        for (int kt = 0; kt < 8; kt++) {
            uint32_t a0, a1, a2, a3;
            ldsm4(a0, a1, a2, a3, abase + kt * 32);
#pragma unroll
            for (int nt = 0; nt < 16; nt++) {
                uint32_t bb0, bb1;
                ldsm2(bb0, bb1, sb + OFF_W1 + (nt * 8 + brow) * XS + kt * 32 + bkoff);
                imma(acc[nt], a0, a1, a2, a3, bb0, bb1);
            }
        }
    }

    // ---- epilogue 1: h = relu(scale*acc + b1); row absmax; requant to int8 smem ----
    int r0 = 16 * w + g, r1 = r0 + 8;
    float sc10 = sS[r0], sc11 = sS[r1];
    float wsc2 = g_wscale2;
    float hm0 = 0.f, hm1 = 0.f;
#pragma unroll
    for (int nt = 0; nt < 16; nt++) {
        int c = nt * 8 + 2 * t;
        float2 bb = *(float2*)(sB1 + c);
        float h0 = fmaxf(sc10 * (float)acc[nt][0] + bb.x, 0.f);
        float h1 = fmaxf(sc10 * (float)acc[nt][1] + bb.y, 0.f);
        float h2 = fmaxf(sc11 * (float)acc[nt][2] + bb.x, 0.f);
        float h3 = fmaxf(sc11 * (float)acc[nt][3] + bb.y, 0.f);
        hm0 = fmaxf(hm0, fmaxf(h0, h1));
        hm1 = fmaxf(hm1, fmaxf(h2, h3));
    }
    hm0 = fmaxf(hm0, __shfl_xor_sync(0xffffffffu, hm0, 1));
    hm0 = fmaxf(hm0, __shfl_xor_sync(0xffffffffu, hm0, 2));
    hm1 = fmaxf(hm1, __shfl_xor_sync(0xffffffffu, hm1, 1));
    hm1 = fmaxf(hm1, __shfl_xor_sync(0xffffffffu, hm1, 2));
    float mc0 = fmaxf(hm0, EPSA), mc1 = fmaxf(hm1, EPSA);
    float s20 = QBF / mc0, s21 = QBF / mc1;
    float scl20 = mc0 * wsc2 * (1.0f / QBF);
    float scl21 = mc1 * wsc2 * (1.0f / QBF);
#pragma unroll
    for (int nt = 0; nt < 16; nt++) {
        int c = nt * 8 + 2 * t;
        float2 bb = *(float2*)(sB1 + c);
        float h0 = fmaxf(sc10 * (float)acc[nt][0] + bb.x, 0.f);
        float h1 = fmaxf(sc10 * (float)acc[nt][1] + bb.y, 0.f);
        float h2 = fmaxf(sc11 * (float)acc[nt][2] + bb.x, 0.f);
        float h3 = fmaxf(sc11 * (float)acc[nt][3] + bb.y, 0.f);
        int q0 = (int)fminf(rintf(h0 * s20), 127.f);   // h >= 0
        int q1 = (int)fminf(rintf(h1 * s20), 127.f);
        int q2 = (int)fminf(rintf(h2 * s21), 127.f);
        int q3 = (int)fminf(rintf(h3 * s21), 127.f);
        *(unsigned short*)(smem + OFF_H + r0 * HS + c) =
            (unsigned short)((q0 & 255) | ((q1 & 255) << 8));
        *(unsigned short*)(smem + OFF_H + r1 * HS + c) =
            (unsigned short)((q2 & 255) | ((q3 & 255) << 8));
    }
    __syncwarp();   // warp-private region of sH: STS -> LDSM ordering within warp

    // ---- GEMM2: [16 x 128] x [128 x 128] per warp ----
#pragma unroll
    for (int nt = 0; nt < 16; nt++)
#pragma unroll
        for (int i = 0; i < 4; i++) acc[nt][i] = 0;
    {
        int arow = 16 * w + (lane & 7) + ((lane >> 3) & 1) * 8;
        uint32_t abase = sb + OFF_H + arow * HS + (lane >> 4) * 16;
        int brow = lane & 7;
        int bkoff = ((lane >> 3) & 1) * 16;
#pragma unroll
        for (int kt = 0; kt < 4; kt++) {
            uint32_t a0, a1, a2, a3;
            ldsm4(a0, a1, a2, a3, abase + kt * 32);
#pragma unroll
            for (int nt = 0; nt < 16; nt++) {
                uint32_t bb0, bb1;
                ldsm2(bb0, bb1, sb + OFF_W2 + (nt * 8 + brow) * HS + kt * 32 + bkoff);
                imma(acc[nt], a0, a1, a2, a3, bb0, bb1);
            }
        }
    }

    // ---- epilogue 2: sigmoid, pu = prior*like, store, column sums ----
    const float* pr0 = prior + (long)(tok0 + r0) * 128;
    const float* pr1 = prior + (long)(tok0 + r1) * 128;
    float* o0 = out + (long)(tok0 + r0) * 128;
    float* o1 = out + (long)(tok0 + r1) * 128;
#pragma unroll
    for (int nt = 0; nt < 16; nt++) {
        int c = nt * 8 + 2 * t;
        float2 bb = *(float2*)(sB2 + c);
        float z0 = scl20 * (float)acc[nt][0] + bb.x;
        float z1 = scl20 * (float)acc[nt][1] + bb.y;
        float z2 = scl21 * (float)acc[nt][2] + bb.x;
        float z3 = scl21 * (float)acc[nt][3] + bb.y;
        float l0 = 1.f / (1.f + expf(-z0));
        float l1 = 1.f / (1.f + expf(-z1));
        float l2 = 1.f / (1.f + expf(-z2));
        float l3 = 1.f / (1.f + expf(-z3));
        float2 p0 = *(const float2*)(pr0 + c);
        float2 p1 = *(const float2*)(pr1 + c);
        float pu0 = p0.x * l0, pu1 = p0.y * l1;
        float pu2 = p1.x * l2, pu3 = p1.y * l3;
        *(float2*)(o0 + c) = make_float2(pu0, pu1);
        *(float2*)(o1 + c) = make_float2(pu2, pu3);
        float cs0 = pu0 + pu2, cs1 = pu1 + pu3;
        cs0 += __shfl_xor_sync(0xffffffffu, cs0, 4);
        cs0 += __shfl_xor_sync(0xffffffffu, cs0, 8);
        cs0 += __shfl_xor_sync(0xffffffffu, cs0, 16);
        cs1 += __shfl_xor_sync(0xffffffffu, cs1, 4);
        cs1 += __shfl_xor_sync(0xffffffffu, cs1, 8);
        cs1 += __shfl_xor_sync(0xffffffffu, cs1, 16);
        if (g == 0) {
            atomicAdd(sCS + c, cs0);
            atomicAdd(sCS + c + 1, cs1);
        }
    }
    __syncthreads();
    if (tid < 128) atomicAdd(g_norm + (tok0 >> 15) * 128 + tid, sCS[tid]);
}

// ---------------- pass 2: out /= clip(norm, 1e-10), in place ----------------
__global__ void div_kernel(float* __restrict__ out) {
    const int total4 = (8 * 32768 * 128) / 4;
    for (int i = blockIdx.x * blockDim.x + threadIdx.x; i < total4;
         i += gridDim.x * blockDim.x) {
        int flat = i << 2;
        int col = flat & 127;
        int b = flat >> 22;          // (token >> 15)
        float4 v = ((float4*)out)[i];
        float4 n = *(const float4*)(g_norm + b * 128 + col);
        v.x /= fmaxf(n.x, 1e-10f);
        v.y /= fmaxf(n.y, 1e-10f);
        v.z /= fmaxf(n.z, 1e-10f);
        v.w /= fmaxf(n.w, 1e-10f);
        ((float4*)out)[i] = v;
    }
}

// ---------------- launch ----------------
extern "C" void kernel_launch(void* const* d_in, const int* in_sizes, int n_in,
                              void* d_out, int out_size) {
    (void)in_sizes; (void)n_in; (void)out_size;
    const float* evidence = (const float*)d_in[0];
    const float* prior    = (const float*)d_in[1];
    const float* W1       = (const float*)d_in[2];
    const float* b1       = (const float*)d_in[3];
    const float* W2       = (const float*)d_in[4];
    const float* b2       = (const float*)d_in[5];
    float* out = (float*)d_out;

    cudaFuncSetAttribute(main_kernel, cudaFuncAttributeMaxDynamicSharedMemorySize, SMEM_BYTES);

    prep_kernel<<<2, 256>>>(W1, W2);
    main_kernel<<<2048, 256, SMEM_BYTES>>>(evidence, prior, b1, b2, out);
    div_kernel<<<4096, 256>>>(out);
}

// round 4
// speedup vs baseline: 1.1219x; 1.1219x over previous
#include <cuda_runtime.h>
#include <cstdint>

#define QBF   127.0f
#define EPSA  1e-5f

// ---------------- device scratch (no allocations allowed) ----------------
__device__ __align__(16) signed char g_W1q[128 * 256];
__device__ __align__(16) signed char g_W2q[128 * 128];
__device__ double g_part[128];
__device__ float g_wscale1;
__device__ float g_wscale2;
__device__ float g_norm[8 * 128];

// ---------------- smem layout for the main kernel ----------------
#define XS 272      // byte stride for 256-byte int8 rows (+16B pad, conflict-free ldmatrix)
#define HS 144      // byte stride for 128-byte int8 rows (+16B pad)
#define OFF_X   0
#define OFF_W1  34816
#define OFF_W2  69632
#define OFF_H   88064
#define OFF_S1  106496
#define OFF_B1  107008
#define OFF_B2  107520
#define OFF_CS  108032
#define SMEM_BYTES 108544

// ---------------- PTX helpers ----------------
__device__ __forceinline__ void ldsm4(uint32_t &r0, uint32_t &r1, uint32_t &r2, uint32_t &r3,
                                      uint32_t addr) {
    asm volatile("ldmatrix.sync.aligned.m8n8.x4.shared.b16 {%0,%1,%2,%3}, [%4];"
                 : "=r"(r0), "=r"(r1), "=r"(r2), "=r"(r3) : "r"(addr));
}
__device__ __forceinline__ void ldsm2(uint32_t &r0, uint32_t &r1, uint32_t addr) {
    asm volatile("ldmatrix.sync.aligned.m8n8.x2.shared.b16 {%0,%1}, [%2];"
                 : "=r"(r0), "=r"(r1) : "r"(addr));
}
__device__ __forceinline__ void imma(int *c, uint32_t a0, uint32_t a1, uint32_t a2, uint32_t a3,
                                     uint32_t b0, uint32_t b1) {
    asm volatile("mma.sync.aligned.m16n8k32.row.col.s32.s8.s8.s32 "
                 "{%0,%1,%2,%3},{%4,%5,%6,%7},{%8,%9},{%0,%1,%2,%3};"
                 : "+r"(c[0]), "+r"(c[1]), "+r"(c[2]), "+r"(c[3])
                 : "r"(a0), "r"(a1), "r"(a2), "r"(a3), "r"(b0), "r"(b1));
}

__device__ __forceinline__ unsigned q4(float4 v, float s) {
    int a = (int)fminf(fmaxf(rintf(v.x * s), -128.f), 127.f);
    int b = (int)fminf(fmaxf(rintf(v.y * s), -128.f), 127.f);
    int c = (int)fminf(fmaxf(rintf(v.z * s), -128.f), 127.f);
    int d = (int)fminf(fmaxf(rintf(v.w * s), -128.f), 127.f);
    return (unsigned)(a & 255) | ((unsigned)(b & 255) << 8) |
           ((unsigned)(c & 255) << 16) | ((unsigned)(d & 255) << 24);
}

// ---------------- prep stage 1: parallel partial |W| sums + zero normalizer ----------------
__global__ void prep_partial(const float* __restrict__ W1, const float* __restrict__ W2) {
    int b = blockIdx.x;                       // 0..127
    const float* W = (b < 64) ? W1 : W2;
    int base = (b < 64) ? b * 512 : (b - 64) * 256;
    int cnt  = (b < 64) ? 512 : 256;
    int tid = threadIdx.x, lane = tid & 31, w = tid >> 5;

    double s = 0.0;
    for (int i = tid; i < cnt; i += 256) s += (double)fabsf(W[base + i]);
#pragma unroll
    for (int o = 16; o; o >>= 1) s += __shfl_xor_sync(0xffffffffu, s, o);
    __shared__ double sh[8];
    if (lane == 0) sh[w] = s;
    __syncthreads();
    if (tid == 0) {
        double t = 0.0;
        for (int i = 0; i < 8; i++) t += sh[i];
        g_part[b] = t;
    }
    if (b < 4) {
        int i = b * 256 + tid;
        if (i < 8 * 128) g_norm[i] = 0.f;
    }
}

// ---------------- prep stage 2: finalize scales + ternary quantize ----------------
__global__ void prep_final(const float* __restrict__ W1, const float* __restrict__ W2) {
    int b = blockIdx.x;                        // 0..95
    double s1 = 0.0, s2 = 0.0;
    for (int i = 0; i < 64; i++) { s1 += g_part[i]; s2 += g_part[64 + i]; }
    float wsc1 = fmaxf((float)(s1 / 32768.0), EPSA);
    float wsc2 = fmaxf((float)(s2 / 16384.0), EPSA);
    if (b == 0 && threadIdx.x == 0) { g_wscale1 = wsc1; g_wscale2 = wsc2; }

    const float* W = (b < 64) ? W1 : W2;
    signed char* dst = (b < 64) ? g_W1q : g_W2q;
    float ws = (b < 64) ? (1.0f / wsc1) : (1.0f / wsc2);
    int base = (b < 64) ? b * 512 : (b - 64) * 512;
    for (int i = threadIdx.x; i < 512; i += 256) {
        float q = fminf(fmaxf(rintf(W[base + i] * ws), -1.f), 1.f);
        dst[base + i] = (signed char)(int)q;
    }
}

// ---------------- fused main: quant -> IMMA GEMM1 -> relu/requant -> IMMA GEMM2
//                  -> sigmoid -> pu = prior * like -> colsum atomics ----------------
__global__ void __launch_bounds__(256, 2)
main_kernel(const float* __restrict__ evidence, const float* __restrict__ prior,
            const float* __restrict__ b1, const float* __restrict__ b2,
            float* __restrict__ out) {
    extern __shared__ char smem[];
    uint32_t sb = (uint32_t)__cvta_generic_to_shared(smem);
    float* sS  = (float*)(smem + OFF_S1);
    float* sB1 = (float*)(smem + OFF_B1);
    float* sB2 = (float*)(smem + OFF_B2);
    float* sCS = (float*)(smem + OFF_CS);

    int tid = threadIdx.x, lane = tid & 31, w = tid >> 5;
    int tok0 = blockIdx.x * 128;

    // ---- phase 0: stage quantized weights + biases into smem ----
    for (int i = tid; i < 128 * 16; i += 256) {
        int r = i >> 4, c = i & 15;
        *(int4*)(smem + OFF_W1 + r * XS + c * 16) = *(const int4*)(g_W1q + r * 256 + c * 16);
    }
    for (int i = tid; i < 128 * 8; i += 256) {
        int r = i >> 3, c = i & 7;
        *(int4*)(smem + OFF_W2 + r * HS + c * 16) = *(const int4*)(g_W2q + r * 128 + c * 16);
    }
    if (tid < 128) { sB1[tid] = b1[tid]; sB2[tid] = b2[tid]; sCS[tid] = 0.f; }

    // ---- phase 1: per-token absmax int8 quant of concat([prior, evidence]) ----
    float wsc1 = g_wscale1;
    for (int rg = 0; rg < 4; rg++) {
        int rbase = 16 * w + rg * 4;
        float4 pv[4], ev[4];
#pragma unroll
        for (int j = 0; j < 4; j++) {
            long gr = (long)(tok0 + rbase + j) * 128;
            pv[j] = *(const float4*)(prior + gr + lane * 4);
            ev[j] = *(const float4*)(evidence + gr + lane * 4);
        }
#pragma unroll
        for (int j = 0; j < 4; j++) {
            float m = fmaxf(fmaxf(fmaxf(fabsf(pv[j].x), fabsf(pv[j].y)),
                                  fmaxf(fabsf(pv[j].z), fabsf(pv[j].w))),
                            fmaxf(fmaxf(fabsf(ev[j].x), fabsf(ev[j].y)),
                                  fmaxf(fabsf(ev[j].z), fabsf(ev[j].w))));
#pragma unroll
            for (int o = 16; o; o >>= 1) m = fmaxf(m, __shfl_xor_sync(0xffffffffu, m, o));
            float mc = fmaxf(m, EPSA);
            float s = QBF / mc;
            int r = rbase + j;
            if (lane == 0) sS[r] = mc * wsc1 * (1.0f / QBF);
            *(unsigned*)(smem + OFF_X + r * XS + lane * 4)       = q4(pv[j], s);
            *(unsigned*)(smem + OFF_X + r * XS + 128 + lane * 4) = q4(ev[j], s);
        }
    }
    __syncthreads();

    // ---- GEMM1: [16 x 256] x [256 x 128] per warp, exact int8 ----
    int acc[16][4];
#pragma unroll
    for (int nt = 0; nt < 16; nt++)
#pragma unroll
        for (int i = 0; i < 4; i++) acc[nt][i] = 0;

    int g = lane >> 2;      // 0..7 (row group)
    int t = lane & 3;       // 0..3 (col pair)
    {
        int arow = 16 * w + (lane & 7) + ((lane >> 3) & 1) * 8;
        uint32_t abase = sb + OFF_X + arow * XS + (lane >> 4) * 16;
        int brow = lane & 7;
        int bkoff = ((lane >> 3) & 1) * 16;
#pragma unroll
        for (int kt = 0; kt < 8; kt++) {
            uint32_t a0, a1, a2, a3;
            ldsm4(a0, a1, a2, a3, abase + kt * 32);
            uint32_t bf[16][2];
#pragma unroll
            for (int nt = 0; nt < 16; nt++)
                ldsm2(bf[nt][0], bf[nt][1],
                      sb + OFF_W1 + (nt * 8 + brow) * XS + kt * 32 + bkoff);
#pragma unroll
            for (int nt = 0; nt < 16; nt++)
                imma(acc[nt], a0, a1, a2, a3, bf[nt][0], bf[nt][1]);
        }
    }

    // ---- epilogue 1: h = relu(scale*acc + b1); row absmax; requant to int8 smem ----
    int r0 = 16 * w + g, r1 = r0 + 8;
    float sc10 = sS[r0], sc11 = sS[r1];
    float wsc2 = g_wscale2;
    float hm0 = 0.f, hm1 = 0.f;
#pragma unroll
    for (int nt = 0; nt < 16; nt++) {
        int c = nt * 8 + 2 * t;
        float2 bb = *(float2*)(sB1 + c);
        float h0 = fmaxf(sc10 * (float)acc[nt][0] + bb.x, 0.f);
        float h1 = fmaxf(sc10 * (float)acc[nt][1] + bb.y, 0.f);
        float h2 = fmaxf(sc11 * (float)acc[nt][2] + bb.x, 0.f);
        float h3 = fmaxf(sc11 * (float)acc[nt][3] + bb.y, 0.f);
        hm0 = fmaxf(hm0, fmaxf(h0, h1));
        hm1 = fmaxf(hm1, fmaxf(h2, h3));
    }
    hm0 = fmaxf(hm0, __shfl_xor_sync(0xffffffffu, hm0, 1));
    hm0 = fmaxf(hm0, __shfl_xor_sync(0xffffffffu, hm0, 2));
    hm1 = fmaxf(hm1, __shfl_xor_sync(0xffffffffu, hm1, 1));
    hm1 = fmaxf(hm1, __shfl_xor_sync(0xffffffffu, hm1, 2));
    float mc0 = fmaxf(hm0, EPSA), mc1 = fmaxf(hm1, EPSA);
    float s20 = QBF / mc0, s21 = QBF / mc1;
    float scl20 = mc0 * wsc2 * (1.0f / QBF);
    float scl21 = mc1 * wsc2 * (1.0f / QBF);
#pragma unroll
    for (int nt = 0; nt < 16; nt++) {
        int c = nt * 8 + 2 * t;
        float2 bb = *(float2*)(sB1 + c);
        float h0 = fmaxf(sc10 * (float)acc[nt][0] + bb.x, 0.f);
        float h1 = fmaxf(sc10 * (float)acc[nt][1] + bb.y, 0.f);
        float h2 = fmaxf(sc11 * (float)acc[nt][2] + bb.x, 0.f);
        float h3 = fmaxf(sc11 * (float)acc[nt][3] + bb.y, 0.f);
        int q0 = (int)fminf(rintf(h0 * s20), 127.f);   // h >= 0
        int q1 = (int)fminf(rintf(h1 * s20), 127.f);
        int q2 = (int)fminf(rintf(h2 * s21), 127.f);
        int q3 = (int)fminf(rintf(h3 * s21), 127.f);
        *(unsigned short*)(smem + OFF_H + r0 * HS + c) =
            (unsigned short)((q0 & 255) | ((q1 & 255) << 8));
        *(unsigned short*)(smem + OFF_H + r1 * HS + c) =
            (unsigned short)((q2 & 255) | ((q3 & 255) << 8));
    }
    __syncwarp();   // warp-private region of sH: STS -> LDSM ordering within warp

    // ---- GEMM2: [16 x 128] x [128 x 128] per warp ----
#pragma unroll
    for (int nt = 0; nt < 16; nt++)
#pragma unroll
        for (int i = 0; i < 4; i++) acc[nt][i] = 0;
    {
        int arow = 16 * w + (lane & 7) + ((lane >> 3) & 1) * 8;
        uint32_t abase = sb + OFF_H + arow * HS + (lane >> 4) * 16;
        int brow = lane & 7;
        int bkoff = ((lane >> 3) & 1) * 16;
#pragma unroll
        for (int kt = 0; kt < 4; kt++) {
            uint32_t a0, a1, a2, a3;
            ldsm4(a0, a1, a2, a3, abase + kt * 32);
            uint32_t bf[16][2];
#pragma unroll
            for (int nt = 0; nt < 16; nt++)
                ldsm2(bf[nt][0], bf[nt][1],
                      sb + OFF_W2 + (nt * 8 + brow) * HS + kt * 32 + bkoff);
#pragma unroll
            for (int nt = 0; nt < 16; nt++)
                imma(acc[nt], a0, a1, a2, a3, bf[nt][0], bf[nt][1]);
        }
    }

    // ---- epilogue 2: sigmoid, pu = prior*like, store, column sums ----
    const float* pr0 = prior + (long)(tok0 + r0) * 128;
    const float* pr1 = prior + (long)(tok0 + r1) * 128;
    float* o0 = out + (long)(tok0 + r0) * 128;
    float* o1 = out + (long)(tok0 + r1) * 128;
#pragma unroll
    for (int nt = 0; nt < 16; nt++) {
        int c = nt * 8 + 2 * t;
        float2 bb = *(float2*)(sB2 + c);
        float z0 = scl20 * (float)acc[nt][0] + bb.x;
        float z1 = scl20 * (float)acc[nt][1] + bb.y;
        float z2 = scl21 * (float)acc[nt][2] + bb.x;
        float z3 = scl21 * (float)acc[nt][3] + bb.y;
        float l0 = __fdividef(1.f, 1.f + __expf(-z0));
        float l1 = __fdividef(1.f, 1.f + __expf(-z1));
        float l2 = __fdividef(1.f, 1.f + __expf(-z2));
        float l3 = __fdividef(1.f, 1.f + __expf(-z3));
        float2 p0 = *(const float2*)(pr0 + c);
        float2 p1 = *(const float2*)(pr1 + c);
        float pu0 = p0.x * l0, pu1 = p0.y * l1;
        float pu2 = p1.x * l2, pu3 = p1.y * l3;
        *(float2*)(o0 + c) = make_float2(pu0, pu1);
        *(float2*)(o1 + c) = make_float2(pu2, pu3);
        float cs0 = pu0 + pu2, cs1 = pu1 + pu3;
        cs0 += __shfl_xor_sync(0xffffffffu, cs0, 4);
        cs0 += __shfl_xor_sync(0xffffffffu, cs0, 8);
        cs0 += __shfl_xor_sync(0xffffffffu, cs0, 16);
        cs1 += __shfl_xor_sync(0xffffffffu, cs1, 4);
        cs1 += __shfl_xor_sync(0xffffffffu, cs1, 8);
        cs1 += __shfl_xor_sync(0xffffffffu, cs1, 16);
        if (g == 0) {
            atomicAdd(sCS + c, cs0);
            atomicAdd(sCS + c + 1, cs1);
        }
    }
    __syncthreads();
    if (tid < 128) atomicAdd(g_norm + (tok0 >> 15) * 128 + tid, sCS[tid]);
}

// ---------------- normalizer reciprocal (1024 values, one block) ----------------
__global__ void recip_kernel() {
    int i = threadIdx.x;
    g_norm[i] = 1.0f / fmaxf(g_norm[i], 1e-10f);
}

// ---------------- pass 2: out *= inv_norm, in place, pure streaming ----------------
__global__ void mul_kernel(float* __restrict__ out) {
    const int total4 = (8 * 32768 * 128) / 4;
    for (int i = blockIdx.x * blockDim.x + threadIdx.x; i < total4;
         i += gridDim.x * blockDim.x) {
        int flat = i << 2;
        int col = flat & 127;
        int b = flat >> 22;          // (token >> 15)
        float4 v = ((float4*)out)[i];
        float4 n = *(const float4*)(g_norm + b * 128 + col);
        v.x *= n.x;
        v.y *= n.y;
        v.z *= n.z;
        v.w *= n.w;
        ((float4*)out)[i] = v;
    }
}

// ---------------- launch ----------------
extern "C" void kernel_launch(void* const* d_in, const int* in_sizes, int n_in,
                              void* d_out, int out_size) {
    (void)in_sizes; (void)n_in; (void)out_size;
    const float* evidence = (const float*)d_in[0];
    const float* prior    = (const float*)d_in[1];
    const float* W1       = (const float*)d_in[2];
    const float* b1       = (const float*)d_in[3];
    const float* W2       = (const float*)d_in[4];
    const float* b2       = (const float*)d_in[5];
    float* out = (float*)d_out;

    cudaFuncSetAttribute(main_kernel, cudaFuncAttributeMaxDynamicSharedMemorySize, SMEM_BYTES);

    prep_partial<<<128, 256>>>(W1, W2);
    prep_final<<<96, 256>>>(W1, W2);
    main_kernel<<<2048, 256, SMEM_BYTES>>>(evidence, prior, b1, b2, out);
    recip_kernel<<<1, 1024>>>();
    mul_kernel<<<4096, 256>>>(out);
}

// round 16
// speedup vs baseline: 1.2076x; 1.0764x over previous
#include <cuda_runtime.h>
#include <cstdint>

#define QBF   127.0f
#define EPSA  1e-5f

// ---------------- device scratch (no allocations allowed) ----------------
__device__ __align__(16) signed char g_W1q[128 * 256];
__device__ __align__(16) signed char g_W2q[128 * 128];
__device__ double g_part[128];
__device__ float g_wscale1;
__device__ float g_wscale2;
__device__ float g_norm[8 * 128];

// ---------------- smem layout for the main kernel ----------------
#define XS 272      // byte stride for 256-byte int8 rows (+16B pad, conflict-free ldmatrix)
#define HS 144      // byte stride for 128-byte int8 rows (+16B pad)
#define OFF_X   0
#define OFF_W1  34816
#define OFF_W2  69632
#define OFF_H   88064
#define OFF_S1  106496
#define OFF_B1  107008
#define OFF_B2  107520
#define OFF_CS  108032
#define SMEM_BYTES 108544

// ---------------- PTX helpers ----------------
__device__ __forceinline__ void ldsm4(uint32_t &r0, uint32_t &r1, uint32_t &r2, uint32_t &r3,
                                      uint32_t addr) {
    asm volatile("ldmatrix.sync.aligned.m8n8.x4.shared.b16 {%0,%1,%2,%3}, [%4];"
                 : "=r"(r0), "=r"(r1), "=r"(r2), "=r"(r3) : "r"(addr));
}
__device__ __forceinline__ void imma(int *c, uint32_t a0, uint32_t a1, uint32_t a2, uint32_t a3,
                                     uint32_t b0, uint32_t b1) {
    asm volatile("mma.sync.aligned.m16n8k32.row.col.s32.s8.s8.s32 "
                 "{%0,%1,%2,%3},{%4,%5,%6,%7},{%8,%9},{%0,%1,%2,%3};"
                 : "+r"(c[0]), "+r"(c[1]), "+r"(c[2]), "+r"(c[3])
                 : "r"(a0), "r"(a1), "r"(a2), "r"(a3), "r"(b0), "r"(b1));
}
// PTX requires the 3-input form for .s8 convert type (same form CUTLASS emits):
// cvt.pack.sat.s8.s32.b32 d, a, b, c  ->  d = (c[15:0]<<16) | sat8(a)<<8 | sat8(b)
// pack two s32 -> saturated s8 pair in low 16 bits: (sat(hi)<<8)|sat(lo)
__device__ __forceinline__ unsigned pack2(int hi, int lo) {
    unsigned r;
    asm("cvt.pack.sat.s8.s32.b32 %0, %1, %2, %3;" : "=r"(r) : "r"(hi), "r"(lo), "r"(0));
    return r;
}
// pack four s32 -> saturated s8 bytes [v0,v1,v2,v3] (little-endian)
__device__ __forceinline__ unsigned pack4(int v0, int v1, int v2, int v3) {
    unsigned t, r;
    asm("cvt.pack.sat.s8.s32.b32 %0, %1, %2, %3;" : "=r"(t) : "r"(v3), "r"(v2), "r"(0));
    asm("cvt.pack.sat.s8.s32.b32 %0, %1, %2, %3;" : "=r"(r) : "r"(v1), "r"(v0), "r"(t));
    return r;
}
__device__ __forceinline__ float tanh_ap(float x) {
    float y;
    asm("tanh.approx.f32 %0, %1;" : "=f"(y) : "f"(x));
    return y;
}
// |x*s| <= 127 by construction: saturation in pack handles the reference clip exactly
__device__ __forceinline__ unsigned q4(float4 v, float s) {
    return pack4(__float2int_rn(v.x * s), __float2int_rn(v.y * s),
                 __float2int_rn(v.z * s), __float2int_rn(v.w * s));
}

// ---------------- prep stage 1: parallel partial |W| sums + zero normalizer ----------------
__global__ void prep_partial(const float* __restrict__ W1, const float* __restrict__ W2) {
    int b = blockIdx.x;                       // 0..127
    const float* W = (b < 64) ? W1 : W2;
    int base = (b < 64) ? b * 512 : (b - 64) * 256;
    int cnt  = (b < 64) ? 512 : 256;
    int tid = threadIdx.x, lane = tid & 31, w = tid >> 5;

    double s = 0.0;
    for (int i = tid; i < cnt; i += 256) s += (double)fabsf(W[base + i]);
#pragma unroll
    for (int o = 16; o; o >>= 1) s += __shfl_xor_sync(0xffffffffu, s, o);
    __shared__ double sh[8];
    if (lane == 0) sh[w] = s;
    __syncthreads();
    if (tid == 0) {
        double t = 0.0;
        for (int i = 0; i < 8; i++) t += sh[i];
        g_part[b] = t;
    }
    if (b < 4) {
        int i = b * 256 + tid;
        if (i < 8 * 128) g_norm[i] = 0.f;
    }
}

// ---------------- prep stage 2: finalize scales + ternary quantize ----------------
__global__ void prep_final(const float* __restrict__ W1, const float* __restrict__ W2) {
    int b = blockIdx.x;                        // 0..95
    double s1 = 0.0, s2 = 0.0;
    for (int i = 0; i < 64; i++) { s1 += g_part[i]; s2 += g_part[64 + i]; }
    float wsc1 = fmaxf((float)(s1 / 32768.0), EPSA);
    float wsc2 = fmaxf((float)(s2 / 16384.0), EPSA);
    if (b == 0 && threadIdx.x == 0) { g_wscale1 = wsc1; g_wscale2 = wsc2; }

    const float* W = (b < 64) ? W1 : W2;
    signed char* dst = (b < 64) ? g_W1q : g_W2q;
    float ws = (b < 64) ? (1.0f / wsc1) : (1.0f / wsc2);
    int base = (b < 64) ? b * 512 : (b - 64) * 512;
    for (int i = threadIdx.x; i < 512; i += 256) {
        float q = fminf(fmaxf(rintf(W[base + i] * ws), -1.f), 1.f);
        dst[base + i] = (signed char)(int)q;
    }
}

// ---------------- fused main: quant -> IMMA GEMM1 -> relu/requant -> IMMA GEMM2
//                  -> sigmoid -> pu = prior * like -> colsum atomics ----------------
__global__ void __launch_bounds__(256, 2)
main_kernel(const float* __restrict__ evidence, const float* __restrict__ prior,
            const float* __restrict__ b1, const float* __restrict__ b2,
            float* __restrict__ out) {
    extern __shared__ char smem[];
    uint32_t sb = (uint32_t)__cvta_generic_to_shared(smem);
    float* sS  = (float*)(smem + OFF_S1);
    float* sB1 = (float*)(smem + OFF_B1);
    float* sB2 = (float*)(smem + OFF_B2);
    float* sCS = (float*)(smem + OFF_CS);

    int tid = threadIdx.x, lane = tid & 31, w = tid >> 5;
    int tok0 = blockIdx.x * 128;

    // ---- phase 0: stage quantized weights + biases into smem ----
    for (int i = tid; i < 128 * 16; i += 256) {
        int r = i >> 4, c = i & 15;
        *(int4*)(smem + OFF_W1 + r * XS + c * 16) = *(const int4*)(g_W1q + r * 256 + c * 16);
    }
    for (int i = tid; i < 128 * 8; i += 256) {
        int r = i >> 3, c = i & 7;
        *(int4*)(smem + OFF_W2 + r * HS + c * 16) = *(const int4*)(g_W2q + r * 128 + c * 16);
    }
    if (tid < 128) { sB1[tid] = b1[tid]; sB2[tid] = 0.5f * b2[tid]; sCS[tid] = 0.f; }

    // ---- phase 1: per-token absmax int8 quant of concat([prior, evidence]) ----
    float wsc1 = g_wscale1;
    for (int rg = 0; rg < 4; rg++) {
        int rbase = 16 * w + rg * 4;
        float4 pv[4], ev[4];
#pragma unroll
        for (int j = 0; j < 4; j++) {
            long gr = (long)(tok0 + rbase + j) * 128;
            pv[j] = *(const float4*)(prior + gr + lane * 4);
            ev[j] = *(const float4*)(evidence + gr + lane * 4);
        }
#pragma unroll
        for (int j = 0; j < 4; j++) {
            float m = fmaxf(fmaxf(fmaxf(fabsf(pv[j].x), fabsf(pv[j].y)),
                                  fmaxf(fabsf(pv[j].z), fabsf(pv[j].w))),
                            fmaxf(fmaxf(fabsf(ev[j].x), fabsf(ev[j].y)),
                                  fmaxf(fabsf(ev[j].z), fabsf(ev[j].w))));
#pragma unroll
            for (int o = 16; o; o >>= 1) m = fmaxf(m, __shfl_xor_sync(0xffffffffu, m, o));
            float mc = fmaxf(m, EPSA);
            float s = QBF / mc;
            int r = rbase + j;
            if (lane == 0) sS[r] = mc * wsc1 * (1.0f / QBF);
            *(unsigned*)(smem + OFF_X + r * XS + lane * 4)       = q4(pv[j], s);
            *(unsigned*)(smem + OFF_X + r * XS + 128 + lane * 4) = q4(ev[j], s);
        }
    }
    __syncthreads();

    // ---- GEMM1: [16 x 256] x [256 x 128] per warp, exact int8 ----
    int acc[16][4];
#pragma unroll
    for (int nt = 0; nt < 16; nt++)
#pragma unroll
        for (int i = 0; i < 4; i++) acc[nt][i] = 0;

    int g = lane >> 2;      // 0..7 (row group)
    int t = lane & 3;       // 0..3 (col pair)
    // B pair-load lane mapping: tiles 0,1 = nt rows (k 0/16), tiles 2,3 = nt+1 rows
    int browp = (lane & 7) + ((lane >> 4) << 3);
    int bko   = ((lane >> 3) & 1) * 16;
    {
        int arow = 16 * w + (lane & 7) + ((lane >> 3) & 1) * 8;
        uint32_t abase = sb + OFF_X + arow * XS + (lane >> 4) * 16;
#pragma unroll
        for (int kt = 0; kt < 8; kt++) {
            uint32_t a0, a1, a2, a3;
            ldsm4(a0, a1, a2, a3, abase + kt * 32);
            uint32_t bf[8][4];
#pragma unroll
            for (int p = 0; p < 8; p++)
                ldsm4(bf[p][0], bf[p][1], bf[p][2], bf[p][3],
                      sb + OFF_W1 + (p * 16 + browp) * XS + kt * 32 + bko);
#pragma unroll
            for (int p = 0; p < 8; p++) {
                imma(acc[2 * p],     a0, a1, a2, a3, bf[p][0], bf[p][1]);
                imma(acc[2 * p + 1], a0, a1, a2, a3, bf[p][2], bf[p][3]);
            }
        }
    }

    // ---- epilogue 1 (single pass): h = relu(scale*acc + b1) kept in regs;
    //      row absmax; requant to int8 smem via saturating pack ----
    int r0 = 16 * w + g, r1 = r0 + 8;
    float sc10 = sS[r0], sc11 = sS[r1];
    float wsc2 = g_wscale2;
    float h[16][4];
    float hm0 = 0.f, hm1 = 0.f;
#pragma unroll
    for (int nt = 0; nt < 16; nt++) {
        int c = nt * 8 + 2 * t;
        float2 bb = *(float2*)(sB1 + c);
        h[nt][0] = fmaxf(sc10 * (float)acc[nt][0] + bb.x, 0.f);
        h[nt][1] = fmaxf(sc10 * (float)acc[nt][1] + bb.y, 0.f);
        h[nt][2] = fmaxf(sc11 * (float)acc[nt][2] + bb.x, 0.f);
        h[nt][3] = fmaxf(sc11 * (float)acc[nt][3] + bb.y, 0.f);
        hm0 = fmaxf(hm0, fmaxf(h[nt][0], h[nt][1]));
        hm1 = fmaxf(hm1, fmaxf(h[nt][2], h[nt][3]));
    }
    hm0 = fmaxf(hm0, __shfl_xor_sync(0xffffffffu, hm0, 1));
    hm0 = fmaxf(hm0, __shfl_xor_sync(0xffffffffu, hm0, 2));
    hm1 = fmaxf(hm1, __shfl_xor_sync(0xffffffffu, hm1, 1));
    hm1 = fmaxf(hm1, __shfl_xor_sync(0xffffffffu, hm1, 2));
    float mc0 = fmaxf(hm0, EPSA), mc1 = fmaxf(hm1, EPSA);
    float s20 = QBF / mc0, s21 = QBF / mc1;
    float scl20 = mc0 * wsc2 * (1.0f / QBF);
    float scl21 = mc1 * wsc2 * (1.0f / QBF);
#pragma unroll
    for (int nt = 0; nt < 16; nt++) {
        int c = nt * 8 + 2 * t;
        *(unsigned short*)(smem + OFF_H + r0 * HS + c) =
            (unsigned short)pack2(__float2int_rn(h[nt][1] * s20),
                                  __float2int_rn(h[nt][0] * s20));
        *(unsigned short*)(smem + OFF_H + r1 * HS + c) =
            (unsigned short)pack2(__float2int_rn(h[nt][3] * s21),
                                  __float2int_rn(h[nt][2] * s21));
    }
    __syncwarp();   // warp-private region of sH: STS -> LDSM ordering within warp

    // ---- GEMM2: [16 x 128] x [128 x 128] per warp ----
#pragma unroll
    for (int nt = 0; nt < 16; nt++)
#pragma unroll
        for (int i = 0; i < 4; i++) acc[nt][i] = 0;
    {
        int arow = 16 * w + (lane & 7) + ((lane >> 3) & 1) * 8;
        uint32_t abase = sb + OFF_H + arow * HS + (lane >> 4) * 16;
#pragma unroll
        for (int kt = 0; kt < 4; kt++) {
            uint32_t a0, a1, a2, a3;
            ldsm4(a0, a1, a2, a3, abase + kt * 32);
            uint32_t bf[8][4];
#pragma unroll
            for (int p = 0; p < 8; p++)
                ldsm4(bf[p][0], bf[p][1], bf[p][2], bf[p][3],
                      sb + OFF_W2 + (p * 16 + browp) * HS + kt * 32 + bko);
#pragma unroll
            for (int p = 0; p < 8; p++) {
                imma(acc[2 * p],     a0, a1, a2, a3, bf[p][0], bf[p][1]);
                imma(acc[2 * p + 1], a0, a1, a2, a3, bf[p][2], bf[p][3]);
            }
        }
    }

    // ---- epilogue 2: sigmoid via tanh, pu = prior*like, store, column sums ----
    // sB2 holds 0.5*b2; z/2 = (0.5*scl)*acc + 0.5*b2; sigma = 0.5*tanh(z/2)+0.5
    float sclh0 = 0.5f * scl20, sclh1 = 0.5f * scl21;
    const float* pr0 = prior + (long)(tok0 + r0) * 128;
    const float* pr1 = prior + (long)(tok0 + r1) * 128;
    float* o0 = out + (long)(tok0 + r0) * 128;
    float* o1 = out + (long)(tok0 + r1) * 128;
#pragma unroll
    for (int nt = 0; nt < 16; nt++) {
        int c = nt * 8 + 2 * t;
        float2 bb = *(float2*)(sB2 + c);
        float l0 = 0.5f * tanh_ap(sclh0 * (float)acc[nt][0] + bb.x) + 0.5f;
        float l1 = 0.5f * tanh_ap(sclh0 * (float)acc[nt][1] + bb.y) + 0.5f;
        float l2 = 0.5f * tanh_ap(sclh1 * (float)acc[nt][2] + bb.x) + 0.5f;
        float l3 = 0.5f * tanh_ap(sclh1 * (float)acc[nt][3] + bb.y) + 0.5f;
        float2 p0 = *(const float2*)(pr0 + c);
        float2 p1 = *(const float2*)(pr1 + c);
        float pu0 = p0.x * l0, pu1 = p0.y * l1;
        float pu2 = p1.x * l2, pu3 = p1.y * l3;
        *(float2*)(o0 + c) = make_float2(pu0, pu1);
        *(float2*)(o1 + c) = make_float2(pu2, pu3);
        float cs0 = pu0 + pu2, cs1 = pu1 + pu3;
        cs0 += __shfl_xor_sync(0xffffffffu, cs0, 4);
        cs0 += __shfl_xor_sync(0xffffffffu, cs0, 8);
        cs0 += __shfl_xor_sync(0xffffffffu, cs0, 16);
        cs1 += __shfl_xor_sync(0xffffffffu, cs1, 4);
        cs1 += __shfl_xor_sync(0xffffffffu, cs1, 8);
        cs1 += __shfl_xor_sync(0xffffffffu, cs1, 16);
        if (g == 0) {
            atomicAdd(sCS + c, cs0);
            atomicAdd(sCS + c + 1, cs1);
        }
    }
    __syncthreads();
    if (tid < 128) atomicAdd(g_norm + (tok0 >> 15) * 128 + tid, sCS[tid]);
}

// ---------------- normalizer reciprocal (1024 values, one block) ----------------
__global__ void recip_kernel() {
    int i = threadIdx.x;
    g_norm[i] = 1.0f / fmaxf(g_norm[i], 1e-10f);
}

// ---------------- pass 2: out *= inv_norm, in place, pure streaming ----------------
__global__ void mul_kernel(float* __restrict__ out) {
    const int total4 = (8 * 32768 * 128) / 4;
    for (int i = blockIdx.x * blockDim.x + threadIdx.x; i < total4;
         i += gridDim.x * blockDim.x) {
        int flat = i << 2;
        int col = flat & 127;
        int b = flat >> 22;          // (token >> 15)
        float4 v = ((float4*)out)[i];
        float4 n = *(const float4*)(g_norm + b * 128 + col);
        v.x *= n.x;
        v.y *= n.y;
        v.z *= n.z;
        v.w *= n.w;
        ((float4*)out)[i] = v;
    }
}

// ---------------- launch ----------------
extern "C" void kernel_launch(void* const* d_in, const int* in_sizes, int n_in,
                              void* d_out, int out_size) {
    (void)in_sizes; (void)n_in; (void)out_size;
    const float* evidence = (const float*)d_in[0];
    const float* prior    = (const float*)d_in[1];
    const float* W1       = (const float*)d_in[2];
    const float* b1       = (const float*)d_in[3];
    const float* W2       = (const float*)d_in[4];
    const float* b2       = (const float*)d_in[5];
    float* out = (float*)d_out;

    cudaFuncSetAttribute(main_kernel, cudaFuncAttributeMaxDynamicSharedMemorySize, SMEM_BYTES);

    prep_partial<<<128, 256>>>(W1, W2);
    prep_final<<<96, 256>>>(W1, W2);
    main_kernel<<<2048, 256, SMEM_BYTES>>>(evidence, prior, b1, b2, out);
    recip_kernel<<<1, 1024>>>();
    mul_kernel<<<4096, 256>>>(out);
}